// round 1
// baseline (speedup 1.0000x reference)
#include <cuda_runtime.h>

// Problem constants (fixed by the reference)
#define NBATCH   2048
#define NVAR     8
#define NTOT     6561      // 3^8
#define NCON     59049     // NTOT * 9
#define BLOCKS_A 64
#define THR_A    32
#define BLOCKS_B 8
#define THR_B    256

// Scratch (allocation-free: __device__ globals)
__device__ float g_Cpart[BLOCKS_A * 9];  // per-block partial sums of Ctot[9]
__device__ float g_Spart[BLOCKS_A];      // per-block partial sums of (P0+P1+P2)
__device__ float g_P0[NBATCH];           // P0 per batch element

// Membership: 1 / (1 + (((x-c)/a)^2)^b), replicating edge cases:
//   x2==0, b>0  -> pow=0 -> mem=1
//   b==0        -> pow=1 -> mem=0.5  (numpy 0**0 == inf**0 == 1)
//   a==0        -> x2=inf -> pow=inf -> mem=0
__device__ __forceinline__ float membership(float x, float a, float b, float c) {
    float u  = (x - c) / a;
    float x2 = u * u;
    float t;
    if (b == 0.0f)       t = 1.0f;
    else if (x2 == 0.0f) t = 0.0f;
    else                 t = exp2f(b * __log2f(x2));
    return 1.0f / (1.0f + t);
}

__global__ __launch_bounds__(THR_A)
void anfis_kA(const float* __restrict__ inp,
              const float* __restrict__ prem,
              const float* __restrict__ conseq) {
    const int tid = threadIdx.x;
    const int bi  = blockIdx.x;

    // ---- Partial reduction of conseq into Ctot[9] ----
    float acc[9];
#pragma unroll
    for (int v = 0; v < 9; v++) acc[v] = 0.0f;

    // groups of 9 consecutive floats; grid-stride over 6561 groups
    for (int g = bi * THR_A + tid; g < NTOT; g += BLOCKS_A * THR_A) {
        const float* p = conseq + 9 * g;
#pragma unroll
        for (int v = 0; v < 9; v++) acc[v] += __ldg(p + v);
    }
#pragma unroll
    for (int v = 0; v < 9; v++) {
#pragma unroll
        for (int o = 16; o > 0; o >>= 1)
            acc[v] += __shfl_down_sync(0xffffffffu, acc[v], o);
    }
    if (tid == 0) {
#pragma unroll
        for (int v = 0; v < 9; v++) g_Cpart[bi * 9 + v] = acc[v];
    }

    // ---- Memberships for one batch element per thread ----
    const int b = bi * THR_A + tid;   // exactly 2048 threads total
    float x[NVAR];
#pragma unroll
    for (int i = 0; i < NVAR; i++) x[i] = __ldg(inp + i * NBATCH + b);

    float P0 = 1.0f, P1 = 1.0f, P2 = 1.0f;
#pragma unroll
    for (int i = 0; i < NVAR; i++) {
        // set j uses premise row s = 3*i + j; row s holds (a, b, c)
        {
            const float* r = prem + 3 * (3 * i + 0);
            P0 *= membership(x[i], __ldg(r + 0), __ldg(r + 1), __ldg(r + 2));
        }
        {
            const float* r = prem + 3 * (3 * i + 1);
            P1 *= membership(x[i], __ldg(r + 0), __ldg(r + 1), __ldg(r + 2));
        }
        {
            const float* r = prem + 3 * (3 * i + 2);
            P2 *= membership(x[i], __ldg(r + 0), __ldg(r + 1), __ldg(r + 2));
        }
    }
    g_P0[b] = P0;

    float S = P0 + P1 + P2;
#pragma unroll
    for (int o = 16; o > 0; o >>= 1)
        S += __shfl_down_sync(0xffffffffu, S, o);
    if (tid == 0) g_Spart[bi] = S;
}

__global__ __launch_bounds__(THR_B)
void anfis_kB(const float* __restrict__ inp, float* __restrict__ out) {
    __shared__ float sC[9];
    __shared__ float sInvZ;
    const int tid = threadIdx.x;

    if (tid < 9) {
        float s = 0.0f;
#pragma unroll
        for (int k = 0; k < BLOCKS_A; k++) s += g_Cpart[k * 9 + tid];
        sC[tid] = s;
    }
    if (tid == 32) {
        float s = 0.0f;
#pragma unroll
        for (int k = 0; k < BLOCKS_A; k++) s += g_Spart[k];
        // Z = sum over (t, b) of fire_strength = 2187 * sum_b (P0+P1+P2)
        sInvZ = 1.0f / (2187.0f * s);
    }
    __syncthreads();

    const int b = blockIdx.x * THR_B + tid;   // 8 * 256 = 2048
    float dot = sC[8];                        // bias row
#pragma unroll
    for (int i = 0; i < NVAR; i++)
        dot += __ldg(inp + i * NBATCH + b) * sC[i];

    out[b] = g_P0[b] * dot * sInvZ;
}

extern "C" void kernel_launch(void* const* d_in, const int* in_sizes, int n_in,
                              void* d_out, int out_size) {
    const float* inp    = (const float*)d_in[0];   // (8, 2048)
    const float* prem   = (const float*)d_in[1];   // (24, 3)
    const float* conseq = (const float*)d_in[2];   // (59049, 1)
    float* out = (float*)d_out;                    // (2048, 1)

    anfis_kA<<<BLOCKS_A, THR_A>>>(inp, prem, conseq);
    anfis_kB<<<BLOCKS_B, THR_B>>>(inp, out);
}

// round 2
// speedup vs baseline: 1.0311x; 1.0311x over previous
#include <cuda_runtime.h>

#define NBATCH 2048
#define NVAR   8
#define NTOT   6561          // 3^8
#define GBLK   16
#define TBLK   128           // 16*128 = 2048 threads = one per batch element

__device__ float g_Cpart[GBLK * 9];
__device__ float g_Spart[GBLK];
__device__ int   g_ctr;      // monotonic barrier ticket counter (never reset)

__device__ __forceinline__ float rcpa(float v) {
    float r; asm("rcp.approx.f32 %0, %1;" : "=f"(r) : "f"(v)); return r;
}
__device__ __forceinline__ float lg2a(float v) {
    float r; asm("lg2.approx.f32 %0, %1;" : "=f"(r) : "f"(v)); return r;
}
__device__ __forceinline__ float ex2a(float v) {
    float r; asm("ex2.approx.f32 %0, %1;" : "=f"(r) : "f"(v)); return r;
}

// Returns (1 + t) with t = ((x-c)/a)^(2b), replicating numpy edge cases:
//   b==0        -> t=1   (0**0 == inf**0 == 1)
//   x2==0, b>0  -> t=0
//   a==0        -> x2=inf -> t=inf (product -> inf -> P=0 via rcp)
__device__ __forceinline__ float one_plus_t(float x, float a, float b, float c) {
    float u  = (x - c) * rcpa(a);
    float x2 = u * u;
    float t;
    if (b == 0.0f)       t = 1.0f;
    else if (x2 == 0.0f) t = 0.0f;
    else                 t = ex2a(b * lg2a(x2));
    return 1.0f + t;
}

__global__ __launch_bounds__(TBLK)
void anfis_fused(const float* __restrict__ inp,
                 const float* __restrict__ prem,
                 const float* __restrict__ conseq,
                 float* __restrict__ out) {
    __shared__ float swC[TBLK / 32][9];
    __shared__ float swS[TBLK / 32];
    __shared__ float sC[9];
    __shared__ float sInvZ;

    const int tid  = threadIdx.x;
    const int bi   = blockIdx.x;
    const int gtid = bi * TBLK + tid;
    const int wid  = tid >> 5, lid = tid & 31;

    // ---- Phase 1a: memberships for this thread's batch element ----
    float x[NVAR];
#pragma unroll
    for (int i = 0; i < NVAR; i++) x[i] = __ldg(inp + i * NBATCH + gtid);

    float q0 = 1.0f, q1 = 1.0f, q2 = 1.0f;   // products of (1+t)
#pragma unroll
    for (int i = 0; i < NVAR; i++) {
        const float* r0 = prem + 3 * (3 * i + 0);
        const float* r1 = prem + 3 * (3 * i + 1);
        const float* r2 = prem + 3 * (3 * i + 2);
        q0 *= one_plus_t(x[i], __ldg(r0), __ldg(r0 + 1), __ldg(r0 + 2));
        q1 *= one_plus_t(x[i], __ldg(r1), __ldg(r1 + 1), __ldg(r1 + 2));
        q2 *= one_plus_t(x[i], __ldg(r2), __ldg(r2 + 1), __ldg(r2 + 2));
    }
    const float P0 = rcpa(q0);               // kept in register across barrier
    float S = P0 + rcpa(q1) + rcpa(q2);

    // ---- Phase 1b: partial reduction of conseq into Ctot[9] ----
    float acc[9];
#pragma unroll
    for (int v = 0; v < 9; v++) acc[v] = 0.0f;
    for (int g = gtid; g < NTOT; g += GBLK * TBLK) {
        const float* p = conseq + 9 * g;
#pragma unroll
        for (int v = 0; v < 9; v++) acc[v] += __ldg(p + v);
    }

    // ---- Block reduce (warp shuffle + smem across 4 warps) ----
#pragma unroll
    for (int v = 0; v < 9; v++) {
#pragma unroll
        for (int o = 16; o > 0; o >>= 1)
            acc[v] += __shfl_down_sync(0xffffffffu, acc[v], o);
    }
#pragma unroll
    for (int o = 16; o > 0; o >>= 1)
        S += __shfl_down_sync(0xffffffffu, S, o);
    if (lid == 0) {
#pragma unroll
        for (int v = 0; v < 9; v++) swC[wid][v] = acc[v];
        swS[wid] = S;
    }
    __syncthreads();

    // ---- Publish partials + grid barrier (monotonic ticket, replay-safe) ----
    if (tid == 0) {
        float cs[9], ss = 0.0f;
#pragma unroll
        for (int v = 0; v < 9; v++) cs[v] = 0.0f;
#pragma unroll
        for (int w = 0; w < TBLK / 32; w++) {
#pragma unroll
            for (int v = 0; v < 9; v++) cs[v] += swC[w][v];
            ss += swS[w];
        }
#pragma unroll
        for (int v = 0; v < 9; v++) g_Cpart[bi * 9 + v] = cs[v];
        g_Spart[bi] = ss;
        __threadfence();
        int ticket = atomicAdd(&g_ctr, 1);
        int target = (ticket / GBLK + 1) * GBLK;  // each launch adds exactly GBLK
        volatile int* vp = &g_ctr;
        while (*vp < target) { }
        __threadfence();
    }
    __syncthreads();

    // ---- Phase 2: fold partials (L2 reads, bypass L1), finalize ----
    if (tid < 9) {
        float s = 0.0f;
#pragma unroll
        for (int k = 0; k < GBLK; k++) s += __ldcg(&g_Cpart[k * 9 + tid]);
        sC[tid] = s;
    }
    if (tid == 32) {
        float s = 0.0f;
#pragma unroll
        for (int k = 0; k < GBLK; k++) s += __ldcg(&g_Spart[k]);
        // Z = sum over (t,b) of fire_strength = 2187 * sum_b (P0+P1+P2)
        sInvZ = 1.0f / (2187.0f * s);
    }
    __syncthreads();

    float dot = sC[8];                        // bias term
#pragma unroll
    for (int i = 0; i < NVAR; i++) dot += x[i] * sC[i];

    out[gtid] = P0 * dot * sInvZ;
}

extern "C" void kernel_launch(void* const* d_in, const int* in_sizes, int n_in,
                              void* d_out, int out_size) {
    const float* inp    = (const float*)d_in[0];   // (8, 2048)
    const float* prem   = (const float*)d_in[1];   // (24, 3)
    const float* conseq = (const float*)d_in[2];   // (59049, 1)
    float* out = (float*)d_out;                    // (2048, 1)

    anfis_fused<<<GBLK, TBLK>>>(inp, prem, conseq, out);
}

// round 3
// speedup vs baseline: 1.2171x; 1.1804x over previous
#include <cuda_runtime.h>

#define NBATCH 2048
#define NVAR   8
#define NTOT   6561          // 3^8
#define NQUAD  1640          // full 4-group quads; group 6560 is the tail
#define GBLK   32
#define TBLK   128           // 32*128 = 4096 threads; 2 threads per batch element

__device__ float g_Cpart[GBLK * 9];
__device__ float g_Spart[GBLK];
__device__ int   g_ctr;      // monotonic barrier ticket counter (never reset)

__device__ __forceinline__ float rcpa(float v) {
    float r; asm("rcp.approx.f32 %0, %1;" : "=f"(r) : "f"(v)); return r;
}
__device__ __forceinline__ float lg2a(float v) {
    float r; asm("lg2.approx.f32 %0, %1;" : "=f"(r) : "f"(v)); return r;
}
__device__ __forceinline__ float ex2a(float v) {
    float r; asm("ex2.approx.f32 %0, %1;" : "=f"(r) : "f"(v)); return r;
}

// (1 + t), t = ((x-c)/a)^(2b), replicating numpy edge cases:
//   b==0        -> t=1   (0**0 == inf**0 == 1)
//   x2==0, b>0  -> t=0
//   a==0        -> x2=inf -> t=inf (product -> inf -> P=0 via rcp)
__device__ __forceinline__ float one_plus_t(float x, float a, float b, float c) {
    float u  = (x - c) * rcpa(a);
    float x2 = u * u;
    float t;
    if (b == 0.0f)       t = 1.0f;
    else if (x2 == 0.0f) t = 0.0f;
    else                 t = ex2a(b * lg2a(x2));
    return 1.0f + t;
}

__global__ __launch_bounds__(TBLK)
void anfis_fused(const float* __restrict__ inp,
                 const float* __restrict__ prem,
                 const float* __restrict__ conseq,
                 float* __restrict__ out) {
    __shared__ float swC[4][9];
    __shared__ float swS[4];
    __shared__ float sC[9];
    __shared__ float sInvZ;

    const int tid  = threadIdx.x;
    const int bi   = blockIdx.x;
    const int w    = tid >> 5, lane = tid & 31;
    const int half = lane >> 4;                  // 0 or 1: which premise half
    const int b    = bi * 64 + w * 16 + (lane & 15);  // batch element

    // ---- Conseq partial reduce: one 144-byte quad (4 groups) per active thread ----
    float acc[9];
#pragma unroll
    for (int v = 0; v < 9; v++) acc[v] = 0.0f;

    const int q = bi + GBLK * tid;               // balanced across blocks
    if (tid < 52 && q < NQUAD) {
        const float4* p = (const float4*)(conseq + 36 * q);
#pragma unroll
        for (int m = 0; m < 9; m++) {
            float4 v = __ldg(p + m);
            acc[(4 * m + 0) % 9] += v.x;
            acc[(4 * m + 1) % 9] += v.y;
            acc[(4 * m + 2) % 9] += v.z;
            acc[(4 * m + 3) % 9] += v.w;
        }
    }
    if (bi == GBLK - 1 && tid == TBLK - 1) {     // tail group 6560
#pragma unroll
        for (int k = 0; k < 9; k++) acc[k] += __ldg(conseq + 36 * NQUAD + k);
    }

    // ---- Memberships: this thread handles 4 of 8 variables for element b ----
    float xo[4];
#pragma unroll
    for (int d = 0; d < 4; d++)
        xo[d] = __ldg(inp + (4 * half + d) * NBATCH + b);

    float q0 = 1.0f, q1 = 1.0f, q2 = 1.0f;       // partial products of (1+t)
#pragma unroll
    for (int d = 0; d < 4; d++) {
        const int i = 4 * half + d;
        const float* r0 = prem + 9 * i;
        q0 *= one_plus_t(xo[d], __ldg(r0 + 0), __ldg(r0 + 1), __ldg(r0 + 2));
        q1 *= one_plus_t(xo[d], __ldg(r0 + 3), __ldg(r0 + 4), __ldg(r0 + 5));
        q2 *= one_plus_t(xo[d], __ldg(r0 + 6), __ldg(r0 + 7), __ldg(r0 + 8));
    }
    // combine halves (paired lanes compute identical products)
    q0 *= __shfl_xor_sync(0xffffffffu, q0, 16);
    q1 *= __shfl_xor_sync(0xffffffffu, q1, 16);
    q2 *= __shfl_xor_sync(0xffffffffu, q2, 16);
    const float P0 = rcpa(q0);
    float S = P0 + rcpa(q1) + rcpa(q2);

    // partner's x values (vars 4..7 for half-0 lanes)
    float xp[4];
#pragma unroll
    for (int d = 0; d < 4; d++)
        xp[d] = __shfl_xor_sync(0xffffffffu, xo[d], 16);

    // ---- Warp reduce acc[9] and S ----
#pragma unroll
    for (int v = 0; v < 9; v++) {
#pragma unroll
        for (int o = 16; o > 0; o >>= 1)
            acc[v] += __shfl_down_sync(0xffffffffu, acc[v], o);
    }
#pragma unroll
    for (int o = 16; o > 0; o >>= 1)
        S += __shfl_down_sync(0xffffffffu, S, o);
    if (lane == 0) {
#pragma unroll
        for (int v = 0; v < 9; v++) swC[w][v] = acc[v];
        swS[w] = S * 0.5f;                       // each element counted twice
    }
    __syncthreads();

    // ---- Parallel publish of this block's partials ----
    if (tid < 9)
        g_Cpart[bi * 9 + tid] = swC[0][tid] + swC[1][tid] + swC[2][tid] + swC[3][tid];
    if (tid == 9)
        g_Spart[bi] = swS[0] + swS[1] + swS[2] + swS[3];
    __threadfence();
    __syncthreads();

    // ---- Grid barrier (monotonic ticket, graph-replay safe) ----
    if (tid == 0) {
        int ticket = atomicAdd(&g_ctr, 1);
        int target = (ticket / GBLK + 1) * GBLK;
        volatile int* vp = &g_ctr;
        while (*vp < target) { }
    }
    __syncthreads();

    // ---- Fold partials (L2 reads, bypass L1) ----
    if (tid < 9) {
        float s = 0.0f;
#pragma unroll
        for (int k = 0; k < GBLK; k++) s += __ldcg(&g_Cpart[k * 9 + tid]);
        sC[tid] = s;
    }
    if (tid == 32) {
        float s = 0.0f;
#pragma unroll
        for (int k = 0; k < GBLK; k++) s += __ldcg(&g_Spart[k]);
        sInvZ = 1.0f / (2187.0f * s);            // Z = 2187 * sum_b (P0+P1+P2)
    }
    __syncthreads();

    // ---- Finalize: half-0 lanes own the output for element b ----
    if (half == 0) {
        float dot = sC[8];                       // bias
#pragma unroll
        for (int d = 0; d < 4; d++) dot += xo[d] * sC[d];
#pragma unroll
        for (int d = 0; d < 4; d++) dot += xp[d] * sC[4 + d];
        out[b] = P0 * dot * sInvZ;
    }
}

extern "C" void kernel_launch(void* const* d_in, const int* in_sizes, int n_in,
                              void* d_out, int out_size) {
    const float* inp    = (const float*)d_in[0];   // (8, 2048)
    const float* prem   = (const float*)d_in[1];   // (24, 3)
    const float* conseq = (const float*)d_in[2];   // (59049, 1)
    float* out = (float*)d_out;                    // (2048, 1)

    anfis_fused<<<GBLK, TBLK>>>(inp, prem, conseq, out);
}

// round 4
// speedup vs baseline: 1.3311x; 1.0936x over previous
#include <cuda_runtime.h>

#define NBATCH 2048
#define NVAR   8
#define NTOT   6561          // 3^8
#define NQUAD  1640          // full 4-group (144B) quads; group 6560 is the tail
#define GBLK   64
#define TBLK   128           // 64*128 = 8192 threads; 4 threads per batch element

__device__ float g_Cpart[GBLK * 9];
__device__ float g_Spart[GBLK];
__device__ int   g_ctr;      // monotonic barrier ticket counter (never reset)

__device__ __forceinline__ float rcpa(float v) {
    float r; asm("rcp.approx.f32 %0, %1;" : "=f"(r) : "f"(v)); return r;
}
__device__ __forceinline__ float lg2a(float v) {
    float r; asm("lg2.approx.f32 %0, %1;" : "=f"(r) : "f"(v)); return r;
}
__device__ __forceinline__ float ex2a(float v) {
    float r; asm("ex2.approx.f32 %0, %1;" : "=f"(r) : "f"(v)); return r;
}

// (1 + t), t = ((x-c)/a)^(2b), replicating numpy edge cases:
//   b==0        -> t=1   (0**0 == inf**0 == 1)
//   x2==0, b>0  -> t=0
//   a==0        -> x2=inf -> t=inf (product -> inf -> P=0 via rcp)
__device__ __forceinline__ float one_plus_t(float x, float a, float b, float c) {
    float u  = (x - c) * rcpa(a);
    float x2 = u * u;
    float t;
    if (b == 0.0f)       t = 1.0f;
    else if (x2 == 0.0f) t = 0.0f;
    else                 t = ex2a(b * lg2a(x2));
    return 1.0f + t;
}

__global__ __launch_bounds__(TBLK)
void anfis_fused(const float* __restrict__ inp,
                 const float* __restrict__ prem,
                 const float* __restrict__ conseq,
                 float* __restrict__ out) {
    __shared__ float swC[4][9];      // phase-1 per-warp partials, reused by fold
    __shared__ float swS[4];
    __shared__ float sC[9];
    __shared__ float sInvZ;

    const int tid  = threadIdx.x;
    const int bi   = blockIdx.x;
    const int w    = tid >> 5, lane = tid & 31;
    const int quarter = lane >> 3;                 // which var pair (0..3)
    const int b    = bi * 32 + w * 8 + (lane & 7); // batch element

    // ---- Issue all global loads up front (MLP overlaps MUFU below) ----
    // Conseq: exactly one 144-byte quad (4 groups of 9) per active thread.
    float4 cv[9];
    const int q = bi + GBLK * tid;                 // balanced across blocks
    const bool qact = (tid < 26) && (q < NQUAD);
    if (qact) {
        const float4* p = (const float4*)(conseq + 36 * q);
#pragma unroll
        for (int m = 0; m < 9; m++) cv[m] = __ldg(p + m);
    }

    const int i0 = 2 * quarter, i1 = i0 + 1;       // this thread's two vars
    const float x0 = __ldg(inp + i0 * NBATCH + b);
    const float x1 = __ldg(inp + i1 * NBATCH + b);
    const float* r = prem + 9 * i0;                // rows 3*i0 .. 3*i0+5
    float pp[18];
#pragma unroll
    for (int k = 0; k < 18; k++) pp[k] = __ldg(r + k);

    // ---- Memberships: 2 vars x 3 sets per thread ----
    float q0 = one_plus_t(x0, pp[0],  pp[1],  pp[2])  * one_plus_t(x1, pp[9],  pp[10], pp[11]);
    float q1 = one_plus_t(x0, pp[3],  pp[4],  pp[5])  * one_plus_t(x1, pp[12], pp[13], pp[14]);
    float q2 = one_plus_t(x0, pp[6],  pp[7],  pp[8])  * one_plus_t(x1, pp[15], pp[16], pp[17]);

    // combine the 4 quarter-lanes (all end with the full 8-var product)
    q0 *= __shfl_xor_sync(0xffffffffu, q0, 8);
    q1 *= __shfl_xor_sync(0xffffffffu, q1, 8);
    q2 *= __shfl_xor_sync(0xffffffffu, q2, 8);
    q0 *= __shfl_xor_sync(0xffffffffu, q0, 16);
    q1 *= __shfl_xor_sync(0xffffffffu, q1, 16);
    q2 *= __shfl_xor_sync(0xffffffffu, q2, 16);
    const float P0 = rcpa(q0);
    float S = (P0 + rcpa(q1) + rcpa(q2)) * 0.25f;  // each element counted 4x

    // gather partner x's for finalize (quarter-0 lanes collect all 8 vars)
    const float xa0 = __shfl_xor_sync(0xffffffffu, x0, 8);
    const float xa1 = __shfl_xor_sync(0xffffffffu, x1, 8);
    const float xb0 = __shfl_xor_sync(0xffffffffu, x0, 16);
    const float xb1 = __shfl_xor_sync(0xffffffffu, x1, 16);
    const float xc0 = __shfl_xor_sync(0xffffffffu, x0, 24);
    const float xc1 = __shfl_xor_sync(0xffffffffu, x1, 24);

    // ---- Accumulate conseq quad into Ctot[9] buckets ----
    float acc[9];
#pragma unroll
    for (int v = 0; v < 9; v++) acc[v] = 0.0f;
    if (qact) {
#pragma unroll
        for (int m = 0; m < 9; m++) {
            acc[(4 * m + 0) % 9] += cv[m].x;
            acc[(4 * m + 1) % 9] += cv[m].y;
            acc[(4 * m + 2) % 9] += cv[m].z;
            acc[(4 * m + 3) % 9] += cv[m].w;
        }
    }
    if (bi == GBLK - 1 && tid == TBLK - 1) {       // tail group 6560
#pragma unroll
        for (int k = 0; k < 9; k++) acc[k] += __ldg(conseq + 36 * NQUAD + k);
    }

    // ---- Warp reduce acc[9] and S ----
#pragma unroll
    for (int v = 0; v < 9; v++) {
#pragma unroll
        for (int o = 16; o > 0; o >>= 1)
            acc[v] += __shfl_down_sync(0xffffffffu, acc[v], o);
    }
#pragma unroll
    for (int o = 16; o > 0; o >>= 1)
        S += __shfl_down_sync(0xffffffffu, S, o);
    if (lane == 0) {
#pragma unroll
        for (int v = 0; v < 9; v++) swC[w][v] = acc[v];
        swS[w] = S;
    }
    __syncthreads();

    // ---- Parallel publish of this block's partials ----
    if (tid < 9)
        g_Cpart[bi * 9 + tid] = swC[0][tid] + swC[1][tid] + swC[2][tid] + swC[3][tid];
    if (tid == 9)
        g_Spart[bi] = swS[0] + swS[1] + swS[2] + swS[3];
    __syncthreads();

    // ---- Grid barrier (monotonic ticket, graph-replay safe) ----
    if (tid == 0) {
        __threadfence();                           // publishes -> L2 before ticket
        int ticket = atomicAdd(&g_ctr, 1);
        int target = (ticket / GBLK + 1) * GBLK;
        volatile int* vp = &g_ctr;
        while (*vp < target) { }
    }
    __syncthreads();

    // ---- Two-level fold of partials (L2 reads, bypass L1) ----
    if (tid < 36) {                                // 4 parts x 9 buckets
        const int v = tid % 9, part = tid / 9;
        float s = 0.0f;
#pragma unroll
        for (int k = 0; k < GBLK / 4; k++)
            s += __ldcg(&g_Cpart[(part * (GBLK / 4) + k) * 9 + v]);
        swC[part][v] = s;
    }
    if (tid >= 40 && tid < 44) {                   // 4 parts of S
        const int part = tid - 40;
        float s = 0.0f;
#pragma unroll
        for (int k = 0; k < GBLK / 4; k++)
            s += __ldcg(&g_Spart[part * (GBLK / 4) + k]);
        swS[part] = s;
    }
    __syncthreads();
    if (tid < 9)
        sC[tid] = swC[0][tid] + swC[1][tid] + swC[2][tid] + swC[3][tid];
    if (tid == 9)
        sInvZ = 1.0f / (2187.0f * (swS[0] + swS[1] + swS[2] + swS[3]));
    __syncthreads();

    // ---- Finalize: quarter-0 lanes own the output for element b ----
    if (quarter == 0) {
        float dot = sC[8];                         // bias
        dot += x0  * sC[0] + x1  * sC[1];
        dot += xa0 * sC[2] + xa1 * sC[3];
        dot += xb0 * sC[4] + xb1 * sC[5];
        dot += xc0 * sC[6] + xc1 * sC[7];
        out[b] = P0 * dot * sInvZ;
    }
}

extern "C" void kernel_launch(void* const* d_in, const int* in_sizes, int n_in,
                              void* d_out, int out_size) {
    const float* inp    = (const float*)d_in[0];   // (8, 2048)
    const float* prem   = (const float*)d_in[1];   // (24, 3)
    const float* conseq = (const float*)d_in[2];   // (59049, 1)
    float* out = (float*)d_out;                    // (2048, 1)

    anfis_fused<<<GBLK, TBLK>>>(inp, prem, conseq, out);
}